// round 16
// baseline (speedup 1.0000x reference)
#include <cuda_runtime.h>
#include <cuda_bf16.h>
#include <cuda_fp16.h>
#include <math.h>
#include <stdint.h>

#define BATCH 512
#define SEQT  200
#define HID   128
#define GATES 512   // 4H
#define EMB   128
#define MTOT  (BATCH*SEQT)   // 102400

// ---------------- static scratch ----------------
__device__ __half g_zx_fw[(size_t)MTOT * GATES];     // fp16 zx
__device__ __half g_zx_bw[(size_t)MTOT * GATES];
__device__ float g_s0f[(size_t)MTOT * HID];
__device__ float g_s0b[(size_t)MTOT * HID];
__device__ float g_s1f[(size_t)MTOT * HID];          // 0.5*(h1 + s0) per direction
__device__ float g_s1b[(size_t)MTOT * HID];
__device__ uint32_t g_xb[(size_t)MTOT * EMB / 2];    // bf16x2 x
__device__ uint32_t g_hb0f[(size_t)MTOT * HID / 2];  // bf16x2 h (fw)
__device__ uint32_t g_hb0b[(size_t)MTOT * HID / 2];  // bf16x2 h (bw)
__device__ uint32_t g_Wtb[4 * GATES * (EMB/2)];      // bf16x2 W^T
__device__ uint32_t g_UfragB[4 * 64 * 4 * 32 * 4];   // bf16 U fragments

// ---------------- helpers ----------------
__device__ __forceinline__ float rcp_(float x) {
    float y; asm("rcp.approx.f32 %0, %1;" : "=f"(y) : "f"(x)); return y;
}
__device__ __forceinline__ float ex2_(float x) {
    float y; asm("ex2.approx.f32 %0, %1;" : "=f"(y) : "f"(x)); return y;
}
__device__ __forceinline__ float sigm(float x) {
    return rcp_(1.f + ex2_(-1.4426950408889634f * x));
}
__device__ __forceinline__ float tanh_(float x) {
    return 1.f - 2.f * rcp_(1.f + ex2_(2.8853900817779268f * x));
}
__device__ __forceinline__ uint32_t bf2(float lo, float hi) {
    __nv_bfloat162 v = __floats2bfloat162_rn(lo, hi);
    return *(uint32_t*)&v;
}
__device__ __forceinline__ uint32_t smem_u32(const void* p) {
    uint32_t a;
    asm("{ .reg .u64 t; cvta.to.shared.u64 t, %1; cvt.u32.u64 %0, t; }" : "=r"(a) : "l"(p));
    return a;
}
__device__ __forceinline__ void cp16(uint32_t s, const void* g) {
    asm volatile("cp.async.cg.shared.global [%0], [%1], 16;" :: "r"(s), "l"(g));
}
__device__ __forceinline__ void ldsm4(uint32_t& d0, uint32_t& d1, uint32_t& d2, uint32_t& d3,
                                      uint32_t addr) {
    asm volatile("ldmatrix.sync.aligned.m8n8.x4.shared.b16 {%0,%1,%2,%3}, [%4];"
        : "=r"(d0), "=r"(d1), "=r"(d2), "=r"(d3) : "r"(addr));
}

__device__ __forceinline__ void mma_bf16(float* d, const uint32_t* a, uint32_t b0, uint32_t b1) {
    asm volatile(
        "mma.sync.aligned.m16n8k16.row.col.f32.bf16.bf16.f32 "
        "{%0,%1,%2,%3}, {%4,%5,%6,%7}, {%8,%9}, {%0,%1,%2,%3};"
        : "+f"(d[0]), "+f"(d[1]), "+f"(d[2]), "+f"(d[3])
        : "r"(a[0]), "r"(a[1]), "r"(a[2]), "r"(a[3]), "r"(b0), "r"(b1));
}

// ---------------- bf16 GEMM: 4-stage cp.async k-pipeline; fw/bw fused via blockIdx.z ----------------
#define LDB2 68
#define TILE_STRIDE (16 * LDB2 * 4)
#define GSMEM (2 * 128 * LDB2 * 4)

__global__ __launch_bounds__(256, 2) void gemm_bf(
    const uint32_t* __restrict__ a_fw, const uint32_t* __restrict__ a_bw,
    const uint32_t* __restrict__ w_fw, const uint32_t* __restrict__ w_bw,
    const float* __restrict__ bias_fw, const float* __restrict__ bias_bw,
    __half* __restrict__ c_fw, __half* __restrict__ c_bw)
{
    const int dir = blockIdx.z;
    const uint32_t* __restrict__ A2  = dir ? a_bw : a_fw;
    const uint32_t* __restrict__ Wtb = dir ? w_bw : w_fw;
    const float* __restrict__ bias   = dir ? bias_bw : bias_fw;
    __half* __restrict__ C           = dir ? c_bw : c_fw;

    extern __shared__ __align__(16) char smem[];
    uint32_t (*As2)[LDB2] = (uint32_t(*)[LDB2])smem;
    uint32_t (*Bs2)[LDB2] = (uint32_t(*)[LDB2])(smem + 128 * LDB2 * 4);

    const int tid = threadIdx.x;
    const int wid = tid >> 5;
    const int lane = tid & 31;
    const int wm = wid & 1;
    const int wn = wid >> 1;
    const int g = lane >> 2;
    const int tig = lane & 3;

    const size_t m0 = (size_t)blockIdx.y * 128;
    const int n0 = blockIdx.x * 128;

#pragma unroll
    for (int h = 0; h < 4; h++) {
#pragma unroll
        for (int i = 0; i < 2; i++) {
            int idx = tid + i * 256;
            int row = idx >> 2;
            int c4  = (idx & 3) + h * 4;
            cp16(smem_u32(&As2[row][c4 * 4]), A2 + (m0 + row) * (EMB/2) + c4 * 4);
            cp16(smem_u32(&Bs2[row][c4 * 4]), Wtb + (size_t)(n0 + row) * (EMB/2) + c4 * 4);
        }
        asm volatile("cp.async.commit_group;");
    }

    const uint32_t a_base = smem_u32(&As2[wm * 64 + (lane & 15)][(lane >> 4) * 4]);
    const uint32_t b_base = smem_u32(&Bs2[wn * 32 + ((lane >> 4) & 1) * 8 + (lane & 7)]
                                        [((lane >> 3) & 1) * 4]);

    float acc[4][4][4];
#pragma unroll
    for (int mt = 0; mt < 4; mt++)
#pragma unroll
        for (int nt = 0; nt < 4; nt++)
#pragma unroll
            for (int q = 0; q < 4; q++) acc[mt][nt][q] = 0.f;

#pragma unroll
    for (int ch = 0; ch < 4; ch++) {
        if (ch == 0) asm volatile("cp.async.wait_group 3;" ::: "memory");
        else if (ch == 1) asm volatile("cp.async.wait_group 2;" ::: "memory");
        else if (ch == 2) asm volatile("cp.async.wait_group 1;" ::: "memory");
        else asm volatile("cp.async.wait_group 0;" ::: "memory");
        __syncthreads();
#pragma unroll
        for (int kk = 0; kk < 2; kk++) {
            const int k8 = ch * 2 + kk;
            const uint32_t koff = k8 * 32;
            uint32_t af[4][4];
#pragma unroll
            for (int mt = 0; mt < 4; mt++)
                ldsm4(af[mt][0], af[mt][1], af[mt][2], af[mt][3],
                      a_base + mt * TILE_STRIDE + koff);
            uint32_t bfv[4][2];
            ldsm4(bfv[0][0], bfv[0][1], bfv[1][0], bfv[1][1], b_base + koff);
            ldsm4(bfv[2][0], bfv[2][1], bfv[3][0], bfv[3][1], b_base + TILE_STRIDE + koff);
#pragma unroll
            for (int nt = 0; nt < 4; nt++)
#pragma unroll
                for (int mt = 0; mt < 4; mt++)
                    mma_bf16(acc[mt][nt], af[mt], bfv[nt][0], bfv[nt][1]);
        }
    }

#pragma unroll
    for (int nt = 0; nt < 4; nt++) {
        int col = n0 + wn * 32 + nt * 8 + 2 * tig;
        float b0 = bias[col], b1 = bias[col + 1];
#pragma unroll
        for (int mt = 0; mt < 4; mt++) {
            size_t row = m0 + wm * 64 + mt * 16 + g;
            __half2 o0 = __floats2half2_rn(acc[mt][nt][0] + b0, acc[mt][nt][1] + b1);
            __half2 o1 = __floats2half2_rn(acc[mt][nt][2] + b0, acc[mt][nt][3] + b1);
            *(__half2*)&C[row * GATES + col] = o0;
            *(__half2*)&C[(row + 8) * GATES + col] = o1;
        }
    }
}

// ---------------- x -> bf16x2 ----------------
__global__ void convert_x(const float* __restrict__ x, uint32_t* __restrict__ xb, int n2)
{
    int i = blockIdx.x * blockDim.x + threadIdx.x;
    if (i < n2) {
        float2 v = ((const float2*)x)[i];
        xb[i] = bf2(v.x, v.y);
    }
}

// ---------------- W -> bf16x2 transposed ----------------
__global__ void build_wtb(const float* __restrict__ W, uint32_t* __restrict__ Wtb)
{
    int idx = blockIdx.x * blockDim.x + threadIdx.x;
    if (idx < 4 * GATES * (EMB/2)) {
        int k2 = idx & 63;
        int n  = (idx >> 6) & 511;
        int u  = idx >> 15;
        const float* Wb = W + (size_t)u * (EMB * GATES);
        Wtb[idx] = bf2(Wb[(size_t)(2*k2) * GATES + n], Wb[(size_t)(2*k2+1) * GATES + n]);
    }
}

// ---------------- bf16 U fragment pre-swizzle ----------------
__global__ void build_ufragb(const float* __restrict__ U, uint32_t* __restrict__ UFB)
{
    int idx = blockIdx.x * blockDim.x + threadIdx.x;
    if (idx < 4 * 64 * 4 * 32 * 4) {
        int q    = idx & 3;
        int lane = (idx >> 2) & 31;
        int kt2  = (idx >> 7) & 3;
        int ntg  = (idx >> 9) & 63;
        int u    = idx >> 15;
        int tig = lane & 3, gg = lane >> 2;
        int kt  = kt2 * 2 + (q >> 1);
        int reg = q & 1;
        int k_lo = kt * 16 + reg * 8 + 2 * tig;
        int n = ntg * 8 + gg;
        const float* Ub = U + (size_t)u * (EMB * GATES);
        UFB[idx] = bf2(Ub[(size_t)k_lo * GATES + n], Ub[(size_t)(k_lo + 1) * GATES + n]);
    }
}

// ---------------- fused bf16 tensor-core LSTM recurrence ----------------
// grid (64, 2), block 512. Layer 1 (add == null): out = h, plus bf16 hb store.
// Layer 2 (add != null): out = 0.5f*(h + add)  (plain store; fw/bw buffers disjoint).
__global__ __launch_bounds__(512) void lstm_tc(
    const __half* __restrict__ zx_fw, const __half* __restrict__ zx_bw,
    const uint32_t* __restrict__ uf_fw, const uint32_t* __restrict__ uf_bw,
    float* __restrict__ out_fw, float* __restrict__ out_bw,
    uint32_t* __restrict__ hb_fw, uint32_t* __restrict__ hb_bw,
    const float* __restrict__ add_fw, const float* __restrict__ add_bw)
{
    const int dir = blockIdx.y;
    const __half* __restrict__ zx = dir ? zx_bw : zx_fw;
    const uint32_t* __restrict__ uf = dir ? uf_bw : uf_fw;
    float* __restrict__ out = dir ? out_bw : out_fw;
    uint32_t* __restrict__ hb = dir ? hb_bw : hb_fw;
    const float* __restrict__ add = dir ? add_bw : add_fw;

    const int b0  = blockIdx.x * 8;
    const int tid = threadIdx.x;
    const int w   = tid >> 5;
    const int lane = tid & 31;
    const int g = lane >> 2;
    const int tig = lane & 3;
    const int col0 = 8 * w + 2 * tig;

    __shared__ __align__(16) uint32_t h2[2][16][68];

    for (int q2 = tid; q2 < 2 * 16 * 68; q2 += 512) ((uint32_t*)h2)[q2] = 0u;
    float c0 = 0.f, c1 = 0.f;

    const uint4* ufp[4];
#pragma unroll
    for (int nt = 0; nt < 4; nt++)
        ufp[nt] = (const uint4*)uf + (size_t)(w + 16 * nt) * 4 * 32 + lane;

    uint32_t h_base[2];
#pragma unroll
    for (int rb2 = 0; rb2 < 2; rb2++)
        h_base[rb2] = smem_u32(&h2[rb2][lane & 15][(lane >> 4) * 4]);

    const size_t rowoff = ((size_t)(b0 + g) * SEQT);
    const __half* zr0 = zx + rowoff * GATES + col0;
    float* or0 = out + rowoff * HID + col0;
    uint32_t* hr0 = hb ? hb + (rowoff * HID + col0) / 2 : (uint32_t*)0;
    const float* ar0 = add ? add + rowoff * HID + col0 : (const float*)0;

    __syncthreads();

    for (int s = 0; s < SEQT; s++) {
        const int t = dir ? (SEQT - 1 - s) : s;
        const int rb = s & 1;
        const int wb = rb ^ 1;

        float2 zv0[4];
#pragma unroll
        for (int nt = 0; nt < 4; nt++) {
            __half2 hz = *(const __half2*)&zr0[(size_t)t * GATES + 128 * nt];
            zv0[nt] = __half22float2(hz);
        }
        float2 av = make_float2(0.f, 0.f);
        if (ar0) av = *(const float2*)&ar0[(size_t)t * HID];

        float acc[4][4];
#pragma unroll
        for (int nt = 0; nt < 4; nt++)
#pragma unroll
            for (int q = 0; q < 4; q++) acc[nt][q] = 0.f;

        uint4 bv[4];
#pragma unroll
        for (int nt = 0; nt < 4; nt++) bv[nt] = ufp[nt][0];

#pragma unroll
        for (int kt2 = 0; kt2 < 4; kt2++) {
            uint4 nb[4];
            if (kt2 < 3) {
#pragma unroll
                for (int nt = 0; nt < 4; nt++) nb[nt] = ufp[nt][(kt2 + 1) * 32];
            }
            uint32_t ae[4], ao[4];
            ldsm4(ae[0], ae[1], ae[2], ae[3], h_base[rb] + kt2 * 64);
            ldsm4(ao[0], ao[1], ao[2], ao[3], h_base[rb] + kt2 * 64 + 32);
#pragma unroll
            for (int nt = 0; nt < 4; nt++) {
                mma_bf16(acc[nt], ae, bv[nt].x, bv[nt].y);
                mma_bf16(acc[nt], ao, bv[nt].z, bv[nt].w);
            }
#pragma unroll
            for (int nt = 0; nt < 4; nt++) bv[nt] = nb[nt];
        }

        float h00, h01;
        {
            float ig = sigm(acc[0][0] + zv0[0].x), fg = sigm(acc[1][0] + zv0[1].x);
            float gg = tanh_(acc[2][0] + zv0[2].x), og = sigm(acc[3][0] + zv0[3].x);
            c0 = fg * c0 + ig * gg;  h00 = og * tanh_(c0);
        }
        {
            float ig = sigm(acc[0][1] + zv0[0].y), fg = sigm(acc[1][1] + zv0[1].y);
            float gg = tanh_(acc[2][1] + zv0[2].y), og = sigm(acc[3][1] + zv0[3].y);
            c1 = fg * c1 + ig * gg;  h01 = og * tanh_(c1);
        }

        uint32_t hp = bf2(h00, h01);
        h2[wb][g][col0 >> 1] = hp;
        if (hr0) hr0[(size_t)t * (HID/2)] = hp;
        float2 ov = ar0 ? make_float2(0.5f * (h00 + av.x), 0.5f * (h01 + av.y))
                        : make_float2(h00, h01);
        *(float2*)&or0[(size_t)t * HID] = ov;

        __syncthreads();
    }
}

// ---------------- final combine: out = a + b ----------------
__global__ void combine2(const float* __restrict__ a, const float* __restrict__ b,
                         float* __restrict__ out, int n4)
{
    int i = blockIdx.x * blockDim.x + threadIdx.x;
    if (i < n4) {
        float4 va = ((const float4*)a)[i];
        float4 vb = ((const float4*)b)[i];
        float4 o;
        o.x = va.x + vb.x;
        o.y = va.y + vb.y;
        o.z = va.z + vb.z;
        o.w = va.w + vb.w;
        ((float4*)out)[i] = o;
    }
}

// ---------------- launch ----------------
extern "C" void kernel_launch(void* const* d_in, const int* in_sizes, int n_in,
                              void* d_out, int out_size)
{
    const float* x = (const float*)d_in[0];
    const float* W = (const float*)d_in[1];
    const float* U = (const float*)d_in[2];
    const float* b = (const float*)d_in[3];

    __half *zxf, *zxb;
    float *s0f, *s0b, *s1f, *s1b;
    uint32_t *xb, *hb0f, *hb0b, *Wtb, *UFB;
    cudaGetSymbolAddress((void**)&zxf, g_zx_fw);
    cudaGetSymbolAddress((void**)&zxb, g_zx_bw);
    cudaGetSymbolAddress((void**)&s0f, g_s0f);
    cudaGetSymbolAddress((void**)&s0b, g_s0b);
    cudaGetSymbolAddress((void**)&s1f, g_s1f);
    cudaGetSymbolAddress((void**)&s1b, g_s1b);
    cudaGetSymbolAddress((void**)&xb, g_xb);
    cudaGetSymbolAddress((void**)&hb0f, g_hb0f);
    cudaGetSymbolAddress((void**)&hb0b, g_hb0b);
    cudaGetSymbolAddress((void**)&Wtb, g_Wtb);
    cudaGetSymbolAddress((void**)&UFB, g_UfragB);

    cudaFuncSetAttribute(gemm_bf, cudaFuncAttributeMaxDynamicSharedMemorySize, GSMEM);

    const size_t WBSZ = (size_t)GATES * (EMB/2);
    const size_t UFSZ = 64 * 4 * 32 * 4;
    const float* b00 = b;           const float* b01 = b + GATES;
    const float* b10 = b + 2*GATES; const float* b11 = b + 3*GATES;
    uint32_t* Wt00 = Wtb;            uint32_t* Wt01 = Wtb + WBSZ;
    uint32_t* Wt10 = Wtb + 2*WBSZ;   uint32_t* Wt11 = Wtb + 3*WBSZ;
    uint32_t* UF00 = UFB;            uint32_t* UF01 = UFB + UFSZ;
    uint32_t* UF10 = UFB + 2*UFSZ;   uint32_t* UF11 = UFB + 3*UFSZ;

    int nx2 = MTOT * EMB / 2;
    int n4 = MTOT * HID / 4;
    convert_x<<<(nx2 + 255) / 256, 256>>>(x, xb, nx2);
    build_wtb<<<(4 * GATES * (EMB/2) + 255) / 256, 256>>>(W, Wtb);
    build_ufragb<<<(4 * 64 * 4 * 32 * 4 + 255) / 256, 256>>>(U, UFB);

    dim3 gg(GATES / 128, MTOT / 128, 2);   // fw+bw fused
    dim3 lg(BATCH / 8, 2);

    gemm_bf<<<gg, 256, GSMEM>>>(xb, xb, Wt00, Wt01, b00, b01, zxf, zxb);
    lstm_tc<<<lg, 512>>>(zxf, zxb, UF00, UF01, s0f, s0b, hb0f, hb0b,
                         (const float*)0, (const float*)0);

    gemm_bf<<<gg, 256, GSMEM>>>(hb0f, hb0b, Wt10, Wt11, b10, b11, zxf, zxb);
    // layer 2: each direction stores 0.5*(h + s0) into its own s1 buffer
    lstm_tc<<<lg, 512>>>(zxf, zxb, UF10, UF11, s1f, s1b,
                         (uint32_t*)0, (uint32_t*)0, s0f, s0b);

    combine2<<<(n4 + 255) / 256, 256>>>(s1f, s1b, (float*)d_out, n4);
}

// round 17
// speedup vs baseline: 1.5519x; 1.5519x over previous
#include <cuda_runtime.h>
#include <cuda_fp16.h>
#include <math.h>
#include <stdint.h>

#define BATCH 512
#define SEQT  200
#define HID   128
#define GATES 512   // 4H
#define EMB   128
#define MTOT  (BATCH*SEQT)   // 102400

// ---------------- static scratch ----------------
__device__ __half g_zx_fw[(size_t)MTOT * GATES];     // fp16 zx
__device__ __half g_zx_bw[(size_t)MTOT * GATES];
__device__ uint32_t g_xh[(size_t)MTOT * EMB / 2];    // fp16x2 x
__device__ uint32_t g_h0f[(size_t)MTOT * HID / 2];   // fp16x2 layer-1 h (fw)
__device__ uint32_t g_h0b[(size_t)MTOT * HID / 2];
__device__ uint32_t g_h1f[(size_t)MTOT * HID / 2];   // fp16x2 layer-2 h (fw)
__device__ uint32_t g_h1b[(size_t)MTOT * HID / 2];
__device__ uint32_t g_Wth[4 * GATES * (EMB/2)];      // fp16x2 W^T: [4][n=512][k2=64]
__device__ uint32_t g_UfragH[4 * 64 * 4 * 32 * 4];   // fp16 U fragments (m16n8k16)

// ---------------- helpers ----------------
__device__ __forceinline__ float rcp_(float x) {
    float y; asm("rcp.approx.f32 %0, %1;" : "=f"(y) : "f"(x)); return y;
}
__device__ __forceinline__ float ex2_(float x) {
    float y; asm("ex2.approx.f32 %0, %1;" : "=f"(y) : "f"(x)); return y;
}
__device__ __forceinline__ float sigm(float x) {
    return rcp_(1.f + ex2_(-1.4426950408889634f * x));
}
__device__ __forceinline__ float tanh_(float x) {
    return 1.f - 2.f * rcp_(1.f + ex2_(2.8853900817779268f * x));
}
__device__ __forceinline__ uint32_t hf2(float lo, float hi) {
    __half2 v = __floats2half2_rn(lo, hi);
    return *(uint32_t*)&v;
}
__device__ __forceinline__ uint32_t smem_u32(const void* p) {
    uint32_t a;
    asm("{ .reg .u64 t; cvta.to.shared.u64 t, %1; cvt.u32.u64 %0, t; }" : "=r"(a) : "l"(p));
    return a;
}
__device__ __forceinline__ void cp16(uint32_t s, const void* g) {
    asm volatile("cp.async.cg.shared.global [%0], [%1], 16;" :: "r"(s), "l"(g));
}
__device__ __forceinline__ void ldsm4(uint32_t& d0, uint32_t& d1, uint32_t& d2, uint32_t& d3,
                                      uint32_t addr) {
    asm volatile("ldmatrix.sync.aligned.m8n8.x4.shared.b16 {%0,%1,%2,%3}, [%4];"
        : "=r"(d0), "=r"(d1), "=r"(d2), "=r"(d3) : "r"(addr));
}

__device__ __forceinline__ void mma_f16(float* d, const uint32_t* a, uint32_t b0, uint32_t b1) {
    asm volatile(
        "mma.sync.aligned.m16n8k16.row.col.f32.f16.f16.f32 "
        "{%0,%1,%2,%3}, {%4,%5,%6,%7}, {%8,%9}, {%0,%1,%2,%3};"
        : "+f"(d[0]), "+f"(d[1]), "+f"(d[2]), "+f"(d[3])
        : "r"(a[0]), "r"(a[1]), "r"(a[2]), "r"(a[3]), "r"(b0), "r"(b1));
}

// ---------------- fp16 GEMM: C[m,n] = A[m,k] @ Wt[n,k]^T + bias[n], C fp16 ----------------
// 2-stage cp.async k-pipeline (measured optimum); fw/bw fused via blockIdx.z.
#define LDB2 68
#define TILE_STRIDE (16 * LDB2 * 4)
#define GSMEM (2 * 128 * LDB2 * 4)

__global__ __launch_bounds__(256, 2) void gemm_hf(
    const uint32_t* __restrict__ a_fw, const uint32_t* __restrict__ a_bw,
    const uint32_t* __restrict__ w_fw, const uint32_t* __restrict__ w_bw,
    const float* __restrict__ bias_fw, const float* __restrict__ bias_bw,
    __half* __restrict__ c_fw, __half* __restrict__ c_bw)
{
    const int dir = blockIdx.z;
    const uint32_t* __restrict__ A2  = dir ? a_bw : a_fw;
    const uint32_t* __restrict__ Wth = dir ? w_bw : w_fw;
    const float* __restrict__ bias   = dir ? bias_bw : bias_fw;
    __half* __restrict__ C           = dir ? c_bw : c_fw;

    extern __shared__ __align__(16) char smem[];
    uint32_t (*As2)[LDB2] = (uint32_t(*)[LDB2])smem;
    uint32_t (*Bs2)[LDB2] = (uint32_t(*)[LDB2])(smem + 128 * LDB2 * 4);

    const int tid = threadIdx.x;
    const int wid = tid >> 5;
    const int lane = tid & 31;
    const int wm = wid & 1;
    const int wn = wid >> 1;
    const int g = lane >> 2;
    const int tig = lane & 3;

    const size_t m0 = (size_t)blockIdx.y * 128;
    const int n0 = blockIdx.x * 128;

    // stage k-half 0 then k-half 1, separate commit groups
#pragma unroll
    for (int h = 0; h < 2; h++) {
#pragma unroll
        for (int i = 0; i < 4; i++) {
            int idx = tid + i * 256;       // 0..1023
            int row = idx >> 3;            // 0..127
            int c4  = (idx & 7) + h * 8;   // chunk index 0..15
            cp16(smem_u32(&As2[row][c4 * 4]), A2 + (m0 + row) * (EMB/2) + c4 * 4);
            cp16(smem_u32(&Bs2[row][c4 * 4]), Wth + (size_t)(n0 + row) * (EMB/2) + c4 * 4);
        }
        asm volatile("cp.async.commit_group;");
    }

    const uint32_t a_base = smem_u32(&As2[wm * 64 + (lane & 15)][(lane >> 4) * 4]);
    const uint32_t b_base = smem_u32(&Bs2[wn * 32 + ((lane >> 4) & 1) * 8 + (lane & 7)]
                                        [((lane >> 3) & 1) * 4]);

    float acc[4][4][4];
#pragma unroll
    for (int mt = 0; mt < 4; mt++)
#pragma unroll
        for (int nt = 0; nt < 4; nt++)
#pragma unroll
            for (int q = 0; q < 4; q++) acc[mt][nt][q] = 0.f;

    asm volatile("cp.async.wait_group 1;" ::: "memory");
    __syncthreads();

#pragma unroll
    for (int k8 = 0; k8 < 4; k8++) {
        const uint32_t koff = k8 * 32;
        uint32_t af[4][4];
#pragma unroll
        for (int mt = 0; mt < 4; mt++)
            ldsm4(af[mt][0], af[mt][1], af[mt][2], af[mt][3],
                  a_base + mt * TILE_STRIDE + koff);
        uint32_t bfv[4][2];
        ldsm4(bfv[0][0], bfv[0][1], bfv[1][0], bfv[1][1], b_base + koff);
        ldsm4(bfv[2][0], bfv[2][1], bfv[3][0], bfv[3][1], b_base + TILE_STRIDE + koff);
#pragma unroll
        for (int nt = 0; nt < 4; nt++)
#pragma unroll
            for (int mt = 0; mt < 4; mt++)
                mma_f16(acc[mt][nt], af[mt], bfv[nt][0], bfv[nt][1]);
    }

    asm volatile("cp.async.wait_group 0;" ::: "memory");
    __syncthreads();

#pragma unroll
    for (int k8 = 4; k8 < 8; k8++) {
        const uint32_t koff = k8 * 32;
        uint32_t af[4][4];
#pragma unroll
        for (int mt = 0; mt < 4; mt++)
            ldsm4(af[mt][0], af[mt][1], af[mt][2], af[mt][3],
                  a_base + mt * TILE_STRIDE + koff);
        uint32_t bfv[4][2];
        ldsm4(bfv[0][0], bfv[0][1], bfv[1][0], bfv[1][1], b_base + koff);
        ldsm4(bfv[2][0], bfv[2][1], bfv[3][0], bfv[3][1], b_base + TILE_STRIDE + koff);
#pragma unroll
        for (int nt = 0; nt < 4; nt++)
#pragma unroll
            for (int mt = 0; mt < 4; mt++)
                mma_f16(acc[mt][nt], af[mt], bfv[nt][0], bfv[nt][1]);
    }

#pragma unroll
    for (int nt = 0; nt < 4; nt++) {
        int col = n0 + wn * 32 + nt * 8 + 2 * tig;
        float b0 = bias[col], b1 = bias[col + 1];
#pragma unroll
        for (int mt = 0; mt < 4; mt++) {
            size_t row = m0 + wm * 64 + mt * 16 + g;
            __half2 o0 = __floats2half2_rn(acc[mt][nt][0] + b0, acc[mt][nt][1] + b1);
            __half2 o1 = __floats2half2_rn(acc[mt][nt][2] + b0, acc[mt][nt][3] + b1);
            *(__half2*)&C[row * GATES + col] = o0;
            *(__half2*)&C[(row + 8) * GATES + col] = o1;
        }
    }
}

// ---------------- x -> fp16x2 ----------------
__global__ void convert_x(const float* __restrict__ x, uint32_t* __restrict__ xh, int n2)
{
    int i = blockIdx.x * blockDim.x + threadIdx.x;
    if (i < n2) {
        float2 v = ((const float2*)x)[i];
        xh[i] = hf2(v.x, v.y);
    }
}

// ---------------- W -> fp16x2 transposed ----------------
__global__ void build_wth(const float* __restrict__ W, uint32_t* __restrict__ Wth)
{
    int idx = blockIdx.x * blockDim.x + threadIdx.x;
    if (idx < 4 * GATES * (EMB/2)) {
        int k2 = idx & 63;
        int n  = (idx >> 6) & 511;
        int u  = idx >> 15;
        const float* Wb = W + (size_t)u * (EMB * GATES);
        Wth[idx] = hf2(Wb[(size_t)(2*k2) * GATES + n], Wb[(size_t)(2*k2+1) * GATES + n]);
    }
}

// ---------------- fp16 U fragment pre-swizzle ----------------
__global__ void build_ufragh(const float* __restrict__ U, uint32_t* __restrict__ UFH)
{
    int idx = blockIdx.x * blockDim.x + threadIdx.x;
    if (idx < 4 * 64 * 4 * 32 * 4) {
        int q    = idx & 3;
        int lane = (idx >> 2) & 31;
        int kt2  = (idx >> 7) & 3;
        int ntg  = (idx >> 9) & 63;
        int u    = idx >> 15;
        int tig = lane & 3, gg = lane >> 2;
        int kt  = kt2 * 2 + (q >> 1);
        int reg = q & 1;
        int k_lo = kt * 16 + reg * 8 + 2 * tig;
        int n = ntg * 8 + gg;
        const float* Ub = U + (size_t)u * (EMB * GATES);
        UFH[idx] = hf2(Ub[(size_t)k_lo * GATES + n], Ub[(size_t)(k_lo + 1) * GATES + n]);
    }
}

// ---------------- fused fp16 tensor-core LSTM recurrence ----------------
// grid (64, 2), block 512. h stored ONLY as fp16x2 (both gemm-A and combine read it).
__global__ __launch_bounds__(512) void lstm_tc(
    const __half* __restrict__ zx_fw, const __half* __restrict__ zx_bw,
    const uint32_t* __restrict__ uf_fw, const uint32_t* __restrict__ uf_bw,
    uint32_t* __restrict__ hb_fw, uint32_t* __restrict__ hb_bw)
{
    const int dir = blockIdx.y;
    const __half* __restrict__ zx = dir ? zx_bw : zx_fw;
    const uint32_t* __restrict__ uf = dir ? uf_bw : uf_fw;
    uint32_t* __restrict__ hb = dir ? hb_bw : hb_fw;

    const int b0  = blockIdx.x * 8;
    const int tid = threadIdx.x;
    const int w   = tid >> 5;
    const int lane = tid & 31;
    const int g = lane >> 2;
    const int tig = lane & 3;
    const int col0 = 8 * w + 2 * tig;

    __shared__ __align__(16) uint32_t h2[2][16][68];

    for (int q2 = tid; q2 < 2 * 16 * 68; q2 += 512) ((uint32_t*)h2)[q2] = 0u;
    float c0 = 0.f, c1 = 0.f;

    const uint4* ufp[4];
#pragma unroll
    for (int nt = 0; nt < 4; nt++)
        ufp[nt] = (const uint4*)uf + (size_t)(w + 16 * nt) * 4 * 32 + lane;

    uint32_t h_base[2];
#pragma unroll
    for (int rb2 = 0; rb2 < 2; rb2++)
        h_base[rb2] = smem_u32(&h2[rb2][lane & 15][(lane >> 4) * 4]);

    const size_t rowoff = ((size_t)(b0 + g) * SEQT);
    const __half* zr0 = zx + rowoff * GATES + col0;
    uint32_t* hr0 = hb + (rowoff * HID + col0) / 2;

    __syncthreads();

    for (int s = 0; s < SEQT; s++) {
        const int t = dir ? (SEQT - 1 - s) : s;
        const int rb = s & 1;
        const int wb = rb ^ 1;

        float2 zv0[4];
#pragma unroll
        for (int nt = 0; nt < 4; nt++) {
            __half2 hz = *(const __half2*)&zr0[(size_t)t * GATES + 128 * nt];
            zv0[nt] = __half22float2(hz);
        }

        float acc[4][4];
#pragma unroll
        for (int nt = 0; nt < 4; nt++)
#pragma unroll
            for (int q = 0; q < 4; q++) acc[nt][q] = 0.f;

        uint4 bv[4];
#pragma unroll
        for (int nt = 0; nt < 4; nt++) bv[nt] = ufp[nt][0];

#pragma unroll
        for (int kt2 = 0; kt2 < 4; kt2++) {
            uint4 nb[4];
            if (kt2 < 3) {
#pragma unroll
                for (int nt = 0; nt < 4; nt++) nb[nt] = ufp[nt][(kt2 + 1) * 32];
            }
            uint32_t ae[4], ao[4];
            ldsm4(ae[0], ae[1], ae[2], ae[3], h_base[rb] + kt2 * 64);
            ldsm4(ao[0], ao[1], ao[2], ao[3], h_base[rb] + kt2 * 64 + 32);
#pragma unroll
            for (int nt = 0; nt < 4; nt++) {
                mma_f16(acc[nt], ae, bv[nt].x, bv[nt].y);
                mma_f16(acc[nt], ao, bv[nt].z, bv[nt].w);
            }
#pragma unroll
            for (int nt = 0; nt < 4; nt++) bv[nt] = nb[nt];
        }

        float h00, h01;
        {
            float ig = sigm(acc[0][0] + zv0[0].x), fg = sigm(acc[1][0] + zv0[1].x);
            float gg = tanh_(acc[2][0] + zv0[2].x), og = sigm(acc[3][0] + zv0[3].x);
            c0 = fg * c0 + ig * gg;  h00 = og * tanh_(c0);
        }
        {
            float ig = sigm(acc[0][1] + zv0[0].y), fg = sigm(acc[1][1] + zv0[1].y);
            float gg = tanh_(acc[2][1] + zv0[2].y), og = sigm(acc[3][1] + zv0[3].y);
            c1 = fg * c1 + ig * gg;  h01 = og * tanh_(c1);
        }

        uint32_t hp = hf2(h00, h01);
        h2[wb][g][col0 >> 1] = hp;
        hr0[(size_t)t * (HID/2)] = hp;

        __syncthreads();
    }
}

// ---------------- final combine: out = 0.5*(h0f + h0b + h1f + h1b), fp16 in / fp32 out ----------------
__global__ void combine4h(const uint2* __restrict__ a, const uint2* __restrict__ b,
                          const uint2* __restrict__ c, const uint2* __restrict__ d,
                          float4* __restrict__ out, int n)
{
    int i = blockIdx.x * blockDim.x + threadIdx.x;
    if (i < n) {
        uint2 ua = a[i], ub = b[i], uc = c[i], ud = d[i];
        float2 a0 = __half22float2(*(__half2*)&ua.x), a1 = __half22float2(*(__half2*)&ua.y);
        float2 b0 = __half22float2(*(__half2*)&ub.x), b1 = __half22float2(*(__half2*)&ub.y);
        float2 c0 = __half22float2(*(__half2*)&uc.x), c1 = __half22float2(*(__half2*)&uc.y);
        float2 d0 = __half22float2(*(__half2*)&ud.x), d1 = __half22float2(*(__half2*)&ud.y);
        float4 o;
        o.x = 0.5f * (a0.x + b0.x + c0.x + d0.x);
        o.y = 0.5f * (a0.y + b0.y + c0.y + d0.y);
        o.z = 0.5f * (a1.x + b1.x + c1.x + d1.x);
        o.w = 0.5f * (a1.y + b1.y + c1.y + d1.y);
        out[i] = o;
    }
}

// ---------------- launch ----------------
extern "C" void kernel_launch(void* const* d_in, const int* in_sizes, int n_in,
                              void* d_out, int out_size)
{
    const float* x = (const float*)d_in[0];
    const float* W = (const float*)d_in[1];
    const float* U = (const float*)d_in[2];
    const float* b = (const float*)d_in[3];

    __half *zxf, *zxb;
    uint32_t *xh, *h0f, *h0b, *h1f, *h1b, *Wth, *UFH;
    cudaGetSymbolAddress((void**)&zxf, g_zx_fw);
    cudaGetSymbolAddress((void**)&zxb, g_zx_bw);
    cudaGetSymbolAddress((void**)&xh, g_xh);
    cudaGetSymbolAddress((void**)&h0f, g_h0f);
    cudaGetSymbolAddress((void**)&h0b, g_h0b);
    cudaGetSymbolAddress((void**)&h1f, g_h1f);
    cudaGetSymbolAddress((void**)&h1b, g_h1b);
    cudaGetSymbolAddress((void**)&Wth, g_Wth);
    cudaGetSymbolAddress((void**)&UFH, g_UfragH);

    cudaFuncSetAttribute(gemm_hf, cudaFuncAttributeMaxDynamicSharedMemorySize, GSMEM);

    const size_t WBSZ = (size_t)GATES * (EMB/2);
    const size_t UFSZ = 64 * 4 * 32 * 4;
    const float* b00 = b;           const float* b01 = b + GATES;
    const float* b10 = b + 2*GATES; const float* b11 = b + 3*GATES;
    uint32_t* Wt00 = Wth;            uint32_t* Wt01 = Wth + WBSZ;
    uint32_t* Wt10 = Wth + 2*WBSZ;   uint32_t* Wt11 = Wth + 3*WBSZ;
    uint32_t* UF00 = UFH;            uint32_t* UF01 = UFH + UFSZ;
    uint32_t* UF10 = UFH + 2*UFSZ;   uint32_t* UF11 = UFH + 3*UFSZ;

    int nx2 = MTOT * EMB / 2;
    int nc = MTOT * HID / 4;
    convert_x<<<(nx2 + 255) / 256, 256>>>(x, xh, nx2);
    build_wth<<<(4 * GATES * (EMB/2) + 255) / 256, 256>>>(W, Wth);
    build_ufragh<<<(4 * 64 * 4 * 32 * 4 + 255) / 256, 256>>>(U, UFH);

    dim3 gg(GATES / 128, MTOT / 128, 2);   // fw+bw fused
    dim3 lg(BATCH / 8, 2);

    gemm_hf<<<gg, 256, GSMEM>>>(xh, xh, Wt00, Wt01, b00, b01, zxf, zxb);
    lstm_tc<<<lg, 512>>>(zxf, zxb, UF00, UF01, h0f, h0b);

    gemm_hf<<<gg, 256, GSMEM>>>(h0f, h0b, Wt10, Wt11, b10, b11, zxf, zxb);
    lstm_tc<<<lg, 512>>>(zxf, zxb, UF10, UF11, h1f, h1b);

    combine4h<<<(nc + 255) / 256, 256>>>((const uint2*)h0f, (const uint2*)h0b,
                                         (const uint2*)h1f, (const uint2*)h1b,
                                         (float4*)d_out, nc);
}